// round 8
// baseline (speedup 1.0000x reference)
#include <cuda_runtime.h>
#include <cuda_bf16.h>
#include <math.h>
#include <stdint.h>
#include <stddef.h>

// Problem constants
#define BB 32
#define NN 1024
#define EE 16384
#define ETOT (EE + NN)
#define IND 768
#define HIDD 512
#define OUTD 400
#define PAIRD 800
#define BNR (BB * NN)          // 32768
#define BER (BB * EE)          // 524288
#define FEAT_ELEMS ((size_t)BNR * OUTD)

typedef __nv_bfloat16 bf16;

#if defined(__CUDA_ARCH_FEAT_SM103_ALL) || defined(__CUDA_ARCH_FEAT_SM100_ALL) || defined(__CUDA_ARCH_FEAT_SM101_ALL)
#define HAS_TC 1
#else
#define HAS_TC 0
#endif

// ---------------- device scratch ----------------
__device__ bf16  g_Xhi[(size_t)BNR * IND];
__device__ bf16  g_Xlo[(size_t)BNR * IND];
__device__ bf16  g_hid_hi[(size_t)BNR * HIDD];
__device__ bf16  g_hid_lo[(size_t)BNR * HIDD];
__device__ float g_enc[(size_t)BNR * OUTD];
__device__ bf16  g_enc_hi[(size_t)BNR * OUTD];
__device__ bf16  g_enc_lo[(size_t)BNR * OUTD];
__device__ float g_wh[(size_t)BNR * OUTD];
__device__ bf16  g_feat_hi[(size_t)BNR * OUTD];
__device__ bf16  g_feat_lo[(size_t)BNR * OUTD];
__device__ float g_U[(size_t)BNR * PAIRD];        // feat @ W1top [32768,800]
__device__ float g_V[(size_t)BNR * PAIRD];        // feat @ W1bot
__device__ float g_P0[(size_t)BER * 3];           // head3 partials (col block 0)
__device__ float g_P1[(size_t)BER * 3];           // head3 partials (col block 1)
// transposed/split weights [N][K]
__device__ bf16  g_w1t_hi[HIDD * IND],  g_w1t_lo[HIDD * IND];
__device__ bf16  g_w2t_hi[OUTD * HIDD], g_w2t_lo[OUTD * HIDD];
__device__ bf16  g_wgt_hi[OUTD * OUTD], g_wgt_lo[OUTD * OUTD];
__device__ bf16  g_w1a_hi[PAIRD * OUTD], g_w1a_lo[PAIRD * OUTD];   // W1top^T [800,400]
__device__ bf16  g_w1b_hi[PAIRD * OUTD], g_w1b_lo[PAIRD * OUTD];   // W1bot^T
__device__ bf16  g_h2t_hi[(PAIRD/2) * PAIRD], g_h2t_lo[(PAIRD/2) * PAIRD];
__device__ float g_as[BNR * 2], g_ad[BNR * 2];
__device__ int   g_counts[NN], g_rowstart[NN + 1], g_fill[NN], g_csrsrc[ETOT];

// gelu(x) = x * sigmoid(2c(x + 0.044715 x^3)) == 0.5x(1+tanh(c(x+0.044715x^3)))
__device__ __forceinline__ float gelu_fast(float x) {
    float x2 = x * x;
    float t2 = x * (-1.5957691216f) * (1.0f + 0.044715f * x2);   // -2c(x+0.044715x^3)
    return x * (1.0f / (1.0f + __expf(t2)));
}

// ---------------- PTX helpers ----------------
__device__ __forceinline__ uint32_t smem_u32(const void* p) {
    uint32_t a;
    asm("{ .reg .u64 t; cvta.to.shared.u64 t, %1; cvt.u32.u64 %0, t; }" : "=r"(a) : "l"(p));
    return a;
}
__device__ __forceinline__ uint32_t elect1() {
    uint32_t r;
    asm volatile("{\n\t.reg .pred p;\n\telect.sync _|p, 0xFFFFFFFF;\n\tselp.b32 %0, 1, 0, p;\n\t}" : "=r"(r));
    return r;
}
#define SW128(o) ((o) ^ (((o) >> 3) & 0x70))

__device__ __forceinline__ uint64_t mk_desc(uint32_t addr) {
    const uint64_t base = (uint64_t(2) << 61) | (uint64_t(1) << 46) |
                          (uint64_t(64) << 32) | (uint64_t(1) << 16);
    return base | ((uint64_t)(addr >> 4) & 0x3FFF);
}

#define MBARRIER_INIT(addr, cnt) \
    asm volatile("mbarrier.init.shared.b64 [%0], %1;" :: "r"((uint32_t)(addr)), "r"((uint32_t)(cnt)) : "memory")

#define MBARRIER_WAIT_PARITY(addr, parity) do { \
    uint32_t _mbar = (uint32_t)(addr); \
    uint32_t _par = (uint32_t)(parity); \
    uint32_t _done; \
    asm volatile("{\n\t.reg .pred p;\n\t" \
        "mbarrier.try_wait.parity.acquire.cta.shared::cta.b64 p, [%1], %2;\n\t" \
        "selp.b32 %0, 1, 0, p;\n\t}" : "=r"(_done) : "r"(_mbar), "r"(_par) : "memory"); \
    if (!_done) { \
        asm volatile("{\n\t.reg .pred P1;\n\t" \
            "WAIT_LOOP_%=:\n\t" \
            "mbarrier.try_wait.parity.acquire.cta.shared::cta.b64 P1, [%0], %1, 0x989680;\n\t" \
            "@P1 bra.uni WAIT_DONE_%=;\n\t" \
            "bra.uni WAIT_LOOP_%=;\n\t" \
            "WAIT_DONE_%=:\n\t}" :: "r"(_mbar), "r"(_par) : "memory"); \
    } \
} while (0)

#if HAS_TC
#define TCGEN05_ALLOC(smem_addr, nCols) \
    asm volatile("tcgen05.alloc.cta_group::1.sync.aligned.shared::cta.b32 [%0], %1;" \
        :: "r"((uint32_t)(smem_addr)), "r"((uint32_t)(nCols)) : "memory")
#define TCGEN05_DEALLOC(tmem, nCols) \
    asm volatile("tcgen05.dealloc.cta_group::1.sync.aligned.b32 %0, %1;" :: "r"(tmem), "r"((uint32_t)(nCols)))
#define TCGEN05_COMMIT(mbar) \
    asm volatile("tcgen05.commit.cta_group::1.mbarrier::arrive::one.shared::cluster.b64 [%0];" \
        :: "r"((uint32_t)(mbar)) : "memory")
#define TCGEN05_FENCE_AFTER() asm volatile("tcgen05.fence::after_thread_sync;" ::: "memory")
#define TCGEN05_WAIT_LD() asm volatile("tcgen05.wait::ld.sync.aligned;" ::: "memory")

#define TCGEN05_LD_32X32B_X32(r, tmem_addr) \
    asm volatile( \
        "tcgen05.ld.sync.aligned.32x32b.x32.b32 " \
        "{%0, %1, %2, %3, %4, %5, %6, %7, " \
        " %8, %9, %10, %11, %12, %13, %14, %15, " \
        " %16, %17, %18, %19, %20, %21, %22, %23, " \
        " %24, %25, %26, %27, %28, %29, %30, %31}, [%32];" \
        : "=r"((r)[0]),  "=r"((r)[1]),  "=r"((r)[2]),  "=r"((r)[3]), \
          "=r"((r)[4]),  "=r"((r)[5]),  "=r"((r)[6]),  "=r"((r)[7]), \
          "=r"((r)[8]),  "=r"((r)[9]),  "=r"((r)[10]), "=r"((r)[11]), \
          "=r"((r)[12]), "=r"((r)[13]), "=r"((r)[14]), "=r"((r)[15]), \
          "=r"((r)[16]), "=r"((r)[17]), "=r"((r)[18]), "=r"((r)[19]), \
          "=r"((r)[20]), "=r"((r)[21]), "=r"((r)[22]), "=r"((r)[23]), \
          "=r"((r)[24]), "=r"((r)[25]), "=r"((r)[26]), "=r"((r)[27]), \
          "=r"((r)[28]), "=r"((r)[29]), "=r"((r)[30]), "=r"((r)[31]) \
        : "r"(tmem_addr))

__device__ __forceinline__ void mma_bf16_ss(uint32_t d, uint64_t ad, uint64_t bd,
                                            uint32_t idesc, uint32_t en) {
    asm volatile(
        "{\n\t.reg .pred p;\n\tsetp.ne.u32 p, %5, 0;\n\t"
        "tcgen05.mma.cta_group::1.kind::f16 [%0], %1, %2, %3, {%4, %4, %4, %4}, p;\n\t}"
        :: "r"(d), "l"(ad), "l"(bd), "r"(idesc), "r"(0u), "r"(en) : "memory");
}
#endif // HAS_TC

// ---------------- prep kernels ----------------
__global__ void split_kernel(const float* __restrict__ in, bf16* __restrict__ hi,
                             bf16* __restrict__ lo, size_t n) {
    size_t i = (size_t)blockIdx.x * 256 + threadIdx.x;
    if (i < n) {
        float v = in[i];
        bf16 h = __float2bfloat16(v);
        hi[i] = h;
        lo[i] = __float2bfloat16(v - __bfloat162float(h));
    }
}
// out[n*Kw+k] = W[(rowOff+k)*ldW + n]  (transpose + split)
__global__ void tsplit_kernel(const float* __restrict__ W, bf16* __restrict__ hi,
                              bf16* __restrict__ lo, int Kw, int Nw, int rowOff, int ldW) {
    int i = blockIdx.x * 256 + threadIdx.x;
    if (i < Kw * Nw) {
        int n = i / Kw, k = i - n * Kw;
        float v = W[(size_t)(rowOff + k) * ldW + n];
        bf16 h = __float2bfloat16(v);
        hi[i] = h;
        lo[i] = __float2bfloat16(v - __bfloat162float(h));
    }
}

// ---------------- split-bf16 tcgen05 GEMM, BM=128, BN<=256, BK=64 ----------------
// MODEA 0: A = hi/lo planes [M,K].
// MODEA 1: A row r = gelu(U[sn]+V[dn]+abias) (fused p1), K=800.
// DOT3: epilogue computes partial dot with w3 -> P0/P1 (no C store).
#define MMK_STAGES 2
#define STAGE_BYTES 98304        // A hi/lo 32KB + B hi/lo 64KB
#define HDR_BYTES 8192
#define SMEM_TOTAL_MM (HDR_BYTES + MMK_STAGES * STAGE_BYTES)
#define CPITCH 65

template<int MODEA, bool BIAS, bool GELU_, bool WF32, bool WHILO, bool DOT3>
__global__ __launch_bounds__(256, 1) void mm_kernel(
    const bf16* __restrict__ Ahi, const bf16* __restrict__ Alo,
    const float* __restrict__ Uf, const float* __restrict__ Vf,
    const bf16* __restrict__ Bhi, const bf16* __restrict__ Blo,
    const float* __restrict__ bias, const float* __restrict__ abias,
    float* __restrict__ Cf, bf16* __restrict__ Chi, bf16* __restrict__ Clo,
    const float* __restrict__ w3, float* __restrict__ P0, float* __restrict__ P1,
    int N, int K,
    const int* __restrict__ src0, const int* __restrict__ dst0)
{
#if HAS_TC
    extern __shared__ char dsm[];
    const int tid = threadIdx.x;
    const int wid = tid >> 5;
    const uint32_t sb = smem_u32(dsm);
    const int mBase = blockIdx.y * 128;
    const int nBase = blockIdx.x * 256;
    const int nValid = min(256, N - nBase);
    int* sSrc = (int*)(dsm + 64);
    int* sDst = (int*)(dsm + 576);
    float* sw3 = (float*)(dsm + 1152);   // up to 256*3 floats

    if (tid == 0) {
        for (int s = 0; s < MMK_STAGES; s++) MBARRIER_INIT(sb + 16 + s * 8, 1);
    }
    if (wid == 0) TCGEN05_ALLOC(sb, 256);
    if (MODEA == 1 && tid < 128) {
        int r = mBase + tid;
        int e = r & (EE - 1);
        int b = r >> 14;
        sSrc[tid] = (b << 10) + src0[e];
        sDst[tid] = (b << 10) + dst0[e];
    }
    if (DOT3) {
        for (int i = tid; i < nValid * 3; i += 256) sw3[i] = w3[nBase * 3 + i];
    }
    __syncthreads();
    uint32_t tmem;
    asm volatile("ld.shared.b32 %0, [%1];" : "=r"(tmem) : "r"(sb));

    const uint32_t idesc = (1u << 4) | (1u << 7) | (1u << 10) |
                           ((uint32_t)(nValid >> 3) << 17) | (8u << 24);
    const int NC = (K + 63) >> 6;

    for (int c = 0; c < NC; c++) {
        int s = c & 1;
        if (c >= MMK_STAGES) {
            MBARRIER_WAIT_PARITY(sb + 16 + s * 8, ((c >> 1) - 1) & 1);
        }
        char* stg = dsm + HDR_BYTES + s * STAGE_BYTES;
        int k0 = c << 6;
        // ---- A planes (128 x 64) ----
        if (MODEA == 0) {
#pragma unroll
            for (int i = 0; i < 4; i++) {
                int idx = i * 256 + tid;
                int row = idx >> 3, seg = idx & 7;
                int col = k0 + seg * 8;
                if (col < K) {
                    size_t off = (size_t)(mBase + row) * K + col;
                    uint4 vh = *(const uint4*)(Ahi + off);
                    uint4 vl = *(const uint4*)(Alo + off);
                    uint32_t sw = SW128(row * 128 + seg * 16);
                    *(uint4*)(stg + sw) = vh;
                    *(uint4*)(stg + 16384 + sw) = vl;
                }
            }
        } else {
            // fused p1: gelu(U[sn]+V[dn]+abias), split hi/lo
#pragma unroll
            for (int i = 0; i < 4; i++) {
                int idx = i * 256 + tid;
                int row = idx >> 3, seg = idx & 7;
                int col = k0 + seg * 8;
                if (col < K) {
                    int sn = sSrc[row], dn = sDst[row];
                    const float* up = Uf + (size_t)sn * PAIRD + col;
                    const float* vp = Vf + (size_t)dn * PAIRD + col;
                    float4 u0 = *(const float4*)up, u1 = *(const float4*)(up + 4);
                    float4 v0 = *(const float4*)vp, v1 = *(const float4*)(vp + 4);
                    float4 b0 = *(const float4*)(abias + col);
                    float4 b1v = *(const float4*)(abias + col + 4);
                    float r[8];
                    r[0] = gelu_fast(u0.x + v0.x + b0.x);
                    r[1] = gelu_fast(u0.y + v0.y + b0.y);
                    r[2] = gelu_fast(u0.z + v0.z + b0.z);
                    r[3] = gelu_fast(u0.w + v0.w + b0.w);
                    r[4] = gelu_fast(u1.x + v1.x + b1v.x);
                    r[5] = gelu_fast(u1.y + v1.y + b1v.y);
                    r[6] = gelu_fast(u1.z + v1.z + b1v.z);
                    r[7] = gelu_fast(u1.w + v1.w + b1v.w);
                    uint32_t hw[4], lw[4];
#pragma unroll
                    for (int q = 0; q < 4; q++) {
                        bf16 h0 = __float2bfloat16(r[q*2+0]);
                        bf16 h1 = __float2bfloat16(r[q*2+1]);
                        bf16 l0 = __float2bfloat16(r[q*2+0] - __bfloat162float(h0));
                        bf16 l1 = __float2bfloat16(r[q*2+1] - __bfloat162float(h1));
                        hw[q] = ((uint32_t)__bfloat16_as_ushort(h1) << 16) | __bfloat16_as_ushort(h0);
                        lw[q] = ((uint32_t)__bfloat16_as_ushort(l1) << 16) | __bfloat16_as_ushort(l0);
                    }
                    uint32_t sw = SW128(row * 128 + seg * 16);
                    *(uint4*)(stg + sw) = make_uint4(hw[0], hw[1], hw[2], hw[3]);
                    *(uint4*)(stg + 16384 + sw) = make_uint4(lw[0], lw[1], lw[2], lw[3]);
                }
            }
        }
        // ---- B planes (nValid x 64) ----
#pragma unroll
        for (int i = 0; i < 8; i++) {
            int idx = i * 256 + tid;
            int row = idx >> 3, seg = idx & 7;
            int col = k0 + seg * 8;
            if (row < nValid && col < K) {
                size_t off = (size_t)(nBase + row) * K + col;
                uint4 vh = *(const uint4*)(Bhi + off);
                uint4 vl = *(const uint4*)(Blo + off);
                uint32_t sw = SW128(row * 128 + seg * 16);
                *(uint4*)(stg + 32768 + sw) = vh;
                *(uint4*)(stg + 65536 + sw) = vl;
            }
        }
        asm volatile("fence.proxy.async.shared::cta;" ::: "memory");
        __syncthreads();
        if (wid == 0 && elect1()) {
            uint32_t sg = sb + HDR_BYTES + s * STAGE_BYTES;
            uint64_t dAh = mk_desc(sg);
            uint64_t dAl = mk_desc(sg + 16384);
            uint64_t dBh = mk_desc(sg + 32768);
            uint64_t dBl = mk_desc(sg + 65536);
            int ksteps = min(4, (K - k0 + 15) >> 4);
            for (int ks = 0; ks < ksteps; ks++) {
                uint64_t o = (uint64_t)(ks * 2);
                mma_bf16_ss(tmem, dAh + o, dBh + o, idesc, (c | ks) ? 1u : 0u);
                mma_bf16_ss(tmem, dAh + o, dBl + o, idesc, 1u);
                mma_bf16_ss(tmem, dAl + o, dBh + o, idesc, 1u);
            }
            TCGEN05_COMMIT(sb + 16 + s * 8);
        }
    }
    {
        int lc = NC - 1;
        MBARRIER_WAIT_PARITY(sb + 16 + (lc & 1) * 8, (lc >> 1) & 1);
    }
    TCGEN05_FENCE_AFTER();

    // ---- epilogue ----
    {
        int sub = wid & 3, cg = wid >> 2;
        int lane = tid & 31;
        float* cst = (float*)(dsm + HDR_BYTES);
        float d0 = 0.f, d1 = 0.f, d2 = 0.f;
        for (int cb0 = 0; cb0 < nValid; cb0 += 64) {
            int cb = cb0 + cg * 32;
            if (cb < nValid) {
                uint32_t regs[32];
                TCGEN05_LD_32X32B_X32(regs, tmem + cb);
                TCGEN05_WAIT_LD();
                int r = sub * 32 + lane;
#pragma unroll
                for (int j = 0; j < 32; j++) {
                    int col = cb + j;
                    if (col < nValid) {
                        float v = __uint_as_float(regs[j]);
                        if (BIAS) v += bias[nBase + col];
                        if (GELU_) v = gelu_fast(v);
                        cst[r * CPITCH + (cg * 32 + j)] = v;
                    }
                }
            }
            __syncthreads();
            int cw = min(64, nValid - cb0);
            if (DOT3) {
                if (tid < 128) {
                    for (int col = 0; col < cw; col++) {
                        float v = cst[tid * CPITCH + col];
                        int wc = (cb0 + col) * 3;
                        d0 += v * sw3[wc + 0];
                        d1 += v * sw3[wc + 1];
                        d2 += v * sw3[wc + 2];
                    }
                }
            } else {
                for (int i = tid; i < 128 * cw; i += 256) {
                    int row = i / cw, col = i - row * cw;
                    float v = cst[row * CPITCH + col];
                    size_t gr = (size_t)(mBase + row);
                    int gc = nBase + cb0 + col;
                    if (WF32) Cf[gr * N + gc] = v;
                    if (WHILO) {
                        bf16 h = __float2bfloat16(v);
                        Chi[gr * N + gc] = h;
                        Clo[gr * N + gc] = __float2bfloat16(v - __bfloat162float(h));
                    }
                }
            }
            __syncthreads();
        }
        if (DOT3 && tid < 128) {
            float* P = (blockIdx.x == 0) ? P0 : P1;
            size_t r = (size_t)(mBase + tid);
            P[r * 3 + 0] = d0;
            P[r * 3 + 1] = d1;
            P[r * 3 + 2] = d2;
        }
    }
    __syncthreads();
    if (wid == 0) TCGEN05_DEALLOC(tmem, 256);

#else // !HAS_TC — naive correct fallback (compile-only for non-'a' PTX pass)
    const int tid = threadIdx.x;
    const int mBase = blockIdx.y * 128;
    const int nBase = blockIdx.x * 256;
    const int nValid = min(256, N - nBase);
    if (tid >= 128) return;
    int row = mBase + tid;
    int sn = 0, dn = 0;
    if (MODEA == 1) {
        int e = row & (EE - 1), b = row >> 14;
        sn = (b << 10) + src0[e];
        dn = (b << 10) + dst0[e];
    }
    float d0 = 0.f, d1 = 0.f, d2 = 0.f;
    for (int col = 0; col < nValid; col++) {
        int gc = nBase + col;
        float acc = 0.f;
        for (int k = 0; k < K; k++) {
            float a;
            if (MODEA == 0) {
                size_t off = (size_t)row * K + k;
                a = __bfloat162float(Ahi[off]) + __bfloat162float(Alo[off]);
            } else {
                a = gelu_fast(Uf[(size_t)sn * PAIRD + k] + Vf[(size_t)dn * PAIRD + k] + abias[k]);
            }
            size_t bo = (size_t)gc * K + k;
            float bb = __bfloat162float(Bhi[bo]) + __bfloat162float(Blo[bo]);
            acc += a * bb;
        }
        if (BIAS) acc += bias[gc];
        if (GELU_) acc = gelu_fast(acc);
        if (DOT3) {
            d0 += acc * w3[gc * 3 + 0];
            d1 += acc * w3[gc * 3 + 1];
            d2 += acc * w3[gc * 3 + 2];
        } else {
            if (WF32) Cf[(size_t)row * N + gc] = acc;
            if (WHILO) {
                bf16 h = __float2bfloat16(acc);
                Chi[(size_t)row * N + gc] = h;
                Clo[(size_t)row * N + gc] = __float2bfloat16(acc - __bfloat162float(h));
            }
        }
    }
    if (DOT3) {
        float* P = (blockIdx.x == 0) ? P0 : P1;
        P[(size_t)row * 3 + 0] = d0;
        P[(size_t)row * 3 + 1] = d1;
        P[(size_t)row * 3 + 2] = d2;
    }
#endif
}

// ---------------- pred = P0 + P1 + b3 ----------------
__global__ void pred_combine_kernel(const float* __restrict__ P0, const float* __restrict__ P1,
                                    const float* __restrict__ b3, float* __restrict__ pred)
{
    int idx = blockIdx.x * 256 + threadIdx.x;
    if (idx < BER * 3) {
        int j = idx % 3;
        pred[idx] = P0[idx] + P1[idx] + b3[j];
    }
}

// ---------------- attention scores ----------------
__global__ void attn_score_kernel(const float* __restrict__ wh,
                                  const float* __restrict__ att_src,
                                  const float* __restrict__ att_dst,
                                  float* __restrict__ as_, float* __restrict__ ad_)
{
    int bn = blockIdx.x;
    int h = threadIdx.x >> 5, lane = threadIdx.x & 31;
    const float* w = wh + (size_t)bn * OUTD + h * 200;
    float s = 0.f, d = 0.f;
    for (int f = lane; f < 200; f += 32) {
        float v = w[f];
        s += v * att_src[h * 200 + f];
        d += v * att_dst[h * 200 + f];
    }
#pragma unroll
    for (int o = 16; o; o >>= 1) {
        s += __shfl_down_sync(0xffffffffu, s, o);
        d += __shfl_down_sync(0xffffffffu, d, o);
    }
    if (lane == 0) { as_[bn * 2 + h] = s; ad_[bn * 2 + h] = d; }
}

// ---------------- CSR build ----------------
__global__ void zero_counts_kernel(int* counts) { counts[threadIdx.x] = 0; }

__global__ void count_kernel(const int* __restrict__ edges, int* __restrict__ counts) {
    int et = blockIdx.x * 256 + threadIdx.x;
    if (et >= ETOT) return;
    int dst = (et < EE) ? edges[EE + et] : (et - EE);
    atomicAdd(&counts[dst], 1);
}

__global__ void scan_kernel(const int* __restrict__ counts, int* __restrict__ rowstart,
                            int* __restrict__ fill) {
    __shared__ int s[NN];
    int t = threadIdx.x;
    int c = counts[t];
    s[t] = c;
    __syncthreads();
    for (int o = 1; o < NN; o <<= 1) {
        int v = (t >= o) ? s[t - o] : 0;
        __syncthreads();
        s[t] += v;
        __syncthreads();
    }
    rowstart[t + 1] = s[t];
    if (t == 0) rowstart[0] = 0;
    fill[t] = s[t] - c;
}

__global__ void scatter_kernel(const int* __restrict__ edges, int* __restrict__ fill,
                               int* __restrict__ csrsrc) {
    int et = blockIdx.x * 256 + threadIdx.x;
    if (et >= ETOT) return;
    int src = (et < EE) ? edges[et] : (et - EE);
    int dst = (et < EE) ? edges[EE + et] : (et - EE);
    int pos = atomicAdd(&fill[dst], 1);
    csrsrc[pos] = src;
}

// ---------------- GAT softmax + aggregation + residual ----------------
#define CHUNK 256
__global__ void gat_kernel(const float* __restrict__ wh, const float* __restrict__ as_,
                           const float* __restrict__ ad_, const float* __restrict__ enc,
                           const float* __restrict__ gat_b,
                           const int* __restrict__ rowstart, const int* __restrict__ csrsrc,
                           float* __restrict__ feat, bf16* __restrict__ feat_hi,
                           bf16* __restrict__ feat_lo)
{
    __shared__ float red0[256], red1[256];
    __shared__ int   s_src[CHUNK];
    __shared__ float s_c0[CHUNK], s_c1[CHUNK];
    __shared__ float sh_m0, sh_m1, sh_z0, sh_z1;

    int bn = blockIdx.x;
    int b = bn >> 10, n = bn & 1023;
    int tid = threadIdx.x;
    int start = rowstart[n];
    int deg = rowstart[n + 1] - start;

    float ad0 = ad_[bn * 2 + 0], ad1 = ad_[bn * 2 + 1];

    float m0 = -1e30f, m1 = -1e30f;
    for (int i = tid; i < deg; i += 256) {
        int s = csrsrc[start + i];
        int sb2 = (b << 10) + s;
        float e0 = as_[sb2 * 2 + 0] + ad0; e0 = (e0 > 0.f) ? e0 : 0.2f * e0;
        float e1 = as_[sb2 * 2 + 1] + ad1; e1 = (e1 > 0.f) ? e1 : 0.2f * e1;
        m0 = fmaxf(m0, e0); m1 = fmaxf(m1, e1);
    }
    red0[tid] = m0; red1[tid] = m1;
    __syncthreads();
    for (int o = 128; o; o >>= 1) {
        if (tid < o) {
            red0[tid] = fmaxf(red0[tid], red0[tid + o]);
            red1[tid] = fmaxf(red1[tid], red1[tid + o]);
        }
        __syncthreads();
    }
    if (tid == 0) { sh_m0 = red0[0]; sh_m1 = red1[0]; }
    __syncthreads();
    m0 = sh_m0; m1 = sh_m1;
    __syncthreads();

    float z0 = 0.f, z1 = 0.f;
    for (int i = tid; i < deg; i += 256) {
        int s = csrsrc[start + i];
        int sb2 = (b << 10) + s;
        float e0 = as_[sb2 * 2 + 0] + ad0; e0 = (e0 > 0.f) ? e0 : 0.2f * e0;
        float e1 = as_[sb2 * 2 + 1] + ad1; e1 = (e1 > 0.f) ? e1 : 0.2f * e1;
        z0 += __expf(e0 - m0);
        z1 += __expf(e1 - m1);
    }
    red0[tid] = z0; red1[tid] = z1;
    __syncthreads();
    for (int o = 128; o; o >>= 1) {
        if (tid < o) { red0[tid] += red0[tid + o]; red1[tid] += red1[tid + o]; }
        __syncthreads();
    }
    if (tid == 0) { sh_z0 = red0[0]; sh_z1 = red1[0]; }
    __syncthreads();
    z0 = sh_z0; z1 = sh_z1;
    float inv0 = 1.f / z0, inv1 = 1.f / z1;

    float acc0 = 0.f, acc1 = 0.f;
    for (int c0 = 0; c0 < deg; c0 += CHUNK) {
        int cn = min(CHUNK, deg - c0);
        __syncthreads();
        if (tid < cn) {
            int s = csrsrc[start + c0 + tid];
            int sb2 = (b << 10) + s;
            float e0 = as_[sb2 * 2 + 0] + ad0; e0 = (e0 > 0.f) ? e0 : 0.2f * e0;
            float e1 = as_[sb2 * 2 + 1] + ad1; e1 = (e1 > 0.f) ? e1 : 0.2f * e1;
            s_src[tid] = sb2;
            s_c0[tid] = __expf(e0 - m0) * inv0;
            s_c1[tid] = __expf(e1 - m1) * inv1;
        }
        __syncthreads();
        for (int i = 0; i < cn; i++) {
            const float* whrow = wh + (size_t)s_src[i] * OUTD;
            float coef = (tid < 200) ? s_c0[i] : s_c1[i];
            acc0 += coef * whrow[tid];
            if (tid < OUTD - 256) acc1 += s_c1[i] * whrow[tid + 256];
        }
    }

    size_t base = (size_t)bn * OUTD;
    {
        float v = enc[base + tid] + acc0 + gat_b[tid];
        feat[base + tid] = v;
        bf16 h = __float2bfloat16(v);
        feat_hi[base + tid] = h;
        feat_lo[base + tid] = __float2bfloat16(v - __bfloat162float(h));
    }
    if (tid < OUTD - 256) {
        float v = enc[base + tid + 256] + acc1 + gat_b[tid + 256];
        feat[base + tid + 256] = v;
        bf16 h = __float2bfloat16(v);
        feat_hi[base + tid + 256] = h;
        feat_lo[base + tid + 256] = __float2bfloat16(v - __bfloat162float(h));
    }
}

// ---------------- launch ----------------
extern "C" void kernel_launch(void* const* d_in, const int* in_sizes, int n_in,
                              void* d_out, int out_size)
{
    const float* X       = (const float*)d_in[0];
    const int*   edges   = (const int*)  d_in[1];
    const float* enc_w1  = (const float*)d_in[2];
    const float* enc_b1  = (const float*)d_in[3];
    const float* enc_w2  = (const float*)d_in[4];
    const float* enc_b2  = (const float*)d_in[5];
    const float* gat_w   = (const float*)d_in[6];
    const float* att_src = (const float*)d_in[7];
    const float* att_dst = (const float*)d_in[8];
    const float* gat_b   = (const float*)d_in[9];
    const float* h_w1    = (const float*)d_in[10];
    const float* h_b1    = (const float*)d_in[11];
    const float* h_w2    = (const float*)d_in[12];
    const float* h_b2    = (const float*)d_in[13];
    const float* h_w3    = (const float*)d_in[14];
    const float* h_b3    = (const float*)d_in[15];

    float* out  = (float*)d_out;
    float* feat = out;
    float* pred = out + FEAT_ELEMS;

    bf16 *Xhi, *Xlo, *hid_hi, *hid_lo, *enc_hi, *enc_lo, *feat_hi, *feat_lo;
    bf16 *w1t_hi, *w1t_lo, *w2t_hi, *w2t_lo, *wgt_hi, *wgt_lo;
    bf16 *w1a_hi, *w1a_lo, *w1b_hi, *w1b_lo, *h2t_hi, *h2t_lo;
    float *enc, *wh, *as_, *ad_, *U, *V, *P0, *P1;
    int *counts, *rowstart, *fill, *csrsrc;
    cudaGetSymbolAddress((void**)&Xhi, g_Xhi);       cudaGetSymbolAddress((void**)&Xlo, g_Xlo);
    cudaGetSymbolAddress((void**)&hid_hi, g_hid_hi); cudaGetSymbolAddress((void**)&hid_lo, g_hid_lo);
    cudaGetSymbolAddress((void**)&enc, g_enc);
    cudaGetSymbolAddress((void**)&enc_hi, g_enc_hi); cudaGetSymbolAddress((void**)&enc_lo, g_enc_lo);
    cudaGetSymbolAddress((void**)&wh, g_wh);
    cudaGetSymbolAddress((void**)&feat_hi, g_feat_hi); cudaGetSymbolAddress((void**)&feat_lo, g_feat_lo);
    cudaGetSymbolAddress((void**)&U, g_U);           cudaGetSymbolAddress((void**)&V, g_V);
    cudaGetSymbolAddress((void**)&P0, g_P0);         cudaGetSymbolAddress((void**)&P1, g_P1);
    cudaGetSymbolAddress((void**)&w1t_hi, g_w1t_hi); cudaGetSymbolAddress((void**)&w1t_lo, g_w1t_lo);
    cudaGetSymbolAddress((void**)&w2t_hi, g_w2t_hi); cudaGetSymbolAddress((void**)&w2t_lo, g_w2t_lo);
    cudaGetSymbolAddress((void**)&wgt_hi, g_wgt_hi); cudaGetSymbolAddress((void**)&wgt_lo, g_wgt_lo);
    cudaGetSymbolAddress((void**)&w1a_hi, g_w1a_hi); cudaGetSymbolAddress((void**)&w1a_lo, g_w1a_lo);
    cudaGetSymbolAddress((void**)&w1b_hi, g_w1b_hi); cudaGetSymbolAddress((void**)&w1b_lo, g_w1b_lo);
    cudaGetSymbolAddress((void**)&h2t_hi, g_h2t_hi); cudaGetSymbolAddress((void**)&h2t_lo, g_h2t_lo);
    cudaGetSymbolAddress((void**)&as_, g_as);        cudaGetSymbolAddress((void**)&ad_, g_ad);
    cudaGetSymbolAddress((void**)&counts, g_counts); cudaGetSymbolAddress((void**)&rowstart, g_rowstart);
    cudaGetSymbolAddress((void**)&fill, g_fill);     cudaGetSymbolAddress((void**)&csrsrc, g_csrsrc);

    const int* src0 = edges;
    const int* dst0 = edges + EE;

    cudaFuncSetAttribute(mm_kernel<0,true ,true ,false,true ,false>, cudaFuncAttributeMaxDynamicSharedMemorySize, SMEM_TOTAL_MM);
    cudaFuncSetAttribute(mm_kernel<0,true ,false,true ,true ,false>, cudaFuncAttributeMaxDynamicSharedMemorySize, SMEM_TOTAL_MM);
    cudaFuncSetAttribute(mm_kernel<0,false,false,true ,false,false>, cudaFuncAttributeMaxDynamicSharedMemorySize, SMEM_TOTAL_MM);
    cudaFuncSetAttribute(mm_kernel<1,true ,true ,false,false,true >, cudaFuncAttributeMaxDynamicSharedMemorySize, SMEM_TOTAL_MM);

    // ---- prep: split X, transpose+split weights ----
    {
        size_t nX = (size_t)BNR * IND;
        split_kernel<<<(unsigned)((nX + 255) / 256), 256>>>(X, Xhi, Xlo, nX);
        tsplit_kernel<<<(IND * HIDD + 255) / 256, 256>>>(enc_w1, w1t_hi, w1t_lo, IND, HIDD, 0, HIDD);
        tsplit_kernel<<<(HIDD * OUTD + 255) / 256, 256>>>(enc_w2, w2t_hi, w2t_lo, HIDD, OUTD, 0, OUTD);
        tsplit_kernel<<<(OUTD * OUTD + 255) / 256, 256>>>(gat_w, wgt_hi, wgt_lo, OUTD, OUTD, 0, OUTD);
        tsplit_kernel<<<(OUTD * PAIRD + 255) / 256, 256>>>(h_w1, w1a_hi, w1a_lo, OUTD, PAIRD, 0, PAIRD);
        tsplit_kernel<<<(OUTD * PAIRD + 255) / 256, 256>>>(h_w1, w1b_hi, w1b_lo, OUTD, PAIRD, OUTD, PAIRD);
        tsplit_kernel<<<(PAIRD * (PAIRD/2) + 255) / 256, 256>>>(h_w2, h2t_hi, h2t_lo, PAIRD, PAIRD/2, 0, PAIRD/2);
    }

    // 1) enc1: [32768,768] -> [32768,512], GELU, write hid hi/lo
    mm_kernel<0,true,true,false,true,false><<<dim3(2, BNR/128), 256, SMEM_TOTAL_MM>>>(
        Xhi, Xlo, nullptr, nullptr, w1t_hi, w1t_lo, enc_b1, nullptr,
        nullptr, hid_hi, hid_lo, nullptr, nullptr, nullptr, HIDD, IND, nullptr, nullptr);
    // 2) enc2: [32768,512] -> [32768,400], write enc f32 + hi/lo
    mm_kernel<0,true,false,true,true,false><<<dim3(2, BNR/128), 256, SMEM_TOTAL_MM>>>(
        hid_hi, hid_lo, nullptr, nullptr, w2t_hi, w2t_lo, enc_b2, nullptr,
        enc, enc_hi, enc_lo, nullptr, nullptr, nullptr, OUTD, HIDD, nullptr, nullptr);
    // 3) wh = enc @ gat_w
    mm_kernel<0,false,false,true,false,false><<<dim3(2, BNR/128), 256, SMEM_TOTAL_MM>>>(
        enc_hi, enc_lo, nullptr, nullptr, wgt_hi, wgt_lo, nullptr, nullptr,
        wh, nullptr, nullptr, nullptr, nullptr, nullptr, OUTD, OUTD, nullptr, nullptr);
    // 4) attention scores
    attn_score_kernel<<<BNR, 64>>>(wh, att_src, att_dst, as_, ad_);
    // 5) CSR build
    zero_counts_kernel<<<1, NN>>>(counts);
    count_kernel<<<(ETOT + 255) / 256, 256>>>(edges, counts);
    scan_kernel<<<1, NN>>>(counts, rowstart, fill);
    scatter_kernel<<<(ETOT + 255) / 256, 256>>>(edges, fill, csrsrc);
    // 6) GAT aggregate + residual -> feat (output) + feat hi/lo
    gat_kernel<<<BNR, 256>>>(wh, as_, ad_, enc, gat_b, rowstart, csrsrc, feat, feat_hi, feat_lo);
    // 7a) U = feat @ W1top: [32768,400] x [400,800]
    mm_kernel<0,false,false,true,false,false><<<dim3(4, BNR/128), 256, SMEM_TOTAL_MM>>>(
        feat_hi, feat_lo, nullptr, nullptr, w1a_hi, w1a_lo, nullptr, nullptr,
        U, nullptr, nullptr, nullptr, nullptr, nullptr, PAIRD, OUTD, nullptr, nullptr);
    // 7b) V = feat @ W1bot
    mm_kernel<0,false,false,true,false,false><<<dim3(4, BNR/128), 256, SMEM_TOTAL_MM>>>(
        feat_hi, feat_lo, nullptr, nullptr, w1b_hi, w1b_lo, nullptr, nullptr,
        V, nullptr, nullptr, nullptr, nullptr, nullptr, PAIRD, OUTD, nullptr, nullptr);
    // 8) head2 fused: A = gelu(U[src]+V[dst]+b1); epilogue = gelu(.+b2) dot W3 -> P0/P1
    mm_kernel<1,true,true,false,false,true><<<dim3(2, BER/128), 256, SMEM_TOTAL_MM>>>(
        nullptr, nullptr, U, V, h2t_hi, h2t_lo, h_b2, h_b1,
        nullptr, nullptr, nullptr, h_w3, P0, P1, PAIRD/2, PAIRD, src0, dst0);
    // 9) pred = P0 + P1 + b3
    pred_combine_kernel<<<(BER * 3 + 255) / 256, 256>>>(P0, P1, h_b3, pred);
}

// round 9
// speedup vs baseline: 1.4269x; 1.4269x over previous
#include <cuda_runtime.h>
#include <cuda_bf16.h>
#include <math.h>
#include <stdint.h>
#include <stddef.h>

// Problem constants
#define BB 32
#define NN 1024
#define EE 16384
#define ETOT (EE + NN)
#define IND 768
#define HIDD 512
#define OUTD 400
#define PAIRD 800
#define BNR (BB * NN)          // 32768
#define BER (BB * EE)          // 524288
#define FEAT_ELEMS ((size_t)BNR * OUTD)

typedef __nv_bfloat16 bf16;

#if defined(__CUDA_ARCH_FEAT_SM103_ALL) || defined(__CUDA_ARCH_FEAT_SM100_ALL) || defined(__CUDA_ARCH_FEAT_SM101_ALL)
#define HAS_TC 1
#else
#define HAS_TC 0
#endif

// ---------------- device scratch ----------------
__device__ bf16  g_Xhi[(size_t)BNR * IND];
__device__ bf16  g_Xlo[(size_t)BNR * IND];
__device__ bf16  g_hid_hi[(size_t)BNR * HIDD];
__device__ bf16  g_hid_lo[(size_t)BNR * HIDD];
__device__ float g_enc[(size_t)BNR * OUTD];
__device__ bf16  g_enc_hi[(size_t)BNR * OUTD];
__device__ bf16  g_enc_lo[(size_t)BNR * OUTD];
__device__ float g_wh[(size_t)BNR * OUTD];
__device__ bf16  g_feat_hi[(size_t)BNR * OUTD];
__device__ bf16  g_feat_lo[(size_t)BNR * OUTD];
__device__ float g_U[(size_t)BNR * PAIRD];        // feat @ W1top [32768,800]
__device__ float g_V[(size_t)BNR * PAIRD];        // feat @ W1bot
// transposed/split weights [N][K]
__device__ bf16  g_w1t_hi[HIDD * IND],  g_w1t_lo[HIDD * IND];
__device__ bf16  g_w2t_hi[OUTD * HIDD], g_w2t_lo[OUTD * HIDD];
__device__ bf16  g_wgt_hi[OUTD * OUTD], g_wgt_lo[OUTD * OUTD];
__device__ bf16  g_w1a_hi[PAIRD * OUTD], g_w1a_lo[PAIRD * OUTD];   // W1top^T [800,400]
__device__ bf16  g_w1b_hi[PAIRD * OUTD], g_w1b_lo[PAIRD * OUTD];   // W1bot^T
__device__ bf16  g_h2t_hi[(PAIRD/2) * PAIRD], g_h2t_lo[(PAIRD/2) * PAIRD];
__device__ float g_as[BNR * 2], g_ad[BNR * 2];
__device__ int   g_counts[NN], g_rowstart[NN + 1], g_fill[NN], g_csrsrc[ETOT];

// tanhf lowers to the HW MUFU.TANH path on sm_103a — measured faster than any
// __expf-based sigmoid form (round-8 isolation test).
__device__ __forceinline__ float gelu_tanh(float x) {
    const float c = 0.7978845608028654f;
    float x3 = x * x * x;
    return 0.5f * x * (1.0f + tanhf(c * (x + 0.044715f * x3)));
}

// ---------------- PTX helpers ----------------
__device__ __forceinline__ uint32_t smem_u32(const void* p) {
    uint32_t a;
    asm("{ .reg .u64 t; cvta.to.shared.u64 t, %1; cvt.u32.u64 %0, t; }" : "=r"(a) : "l"(p));
    return a;
}
__device__ __forceinline__ uint32_t elect1() {
    uint32_t r;
    asm volatile("{\n\t.reg .pred p;\n\telect.sync _|p, 0xFFFFFFFF;\n\tselp.b32 %0, 1, 0, p;\n\t}" : "=r"(r));
    return r;
}
#define SW128(o) ((o) ^ (((o) >> 3) & 0x70))

__device__ __forceinline__ uint64_t mk_desc(uint32_t addr) {
    const uint64_t base = (uint64_t(2) << 61) | (uint64_t(1) << 46) |
                          (uint64_t(64) << 32) | (uint64_t(1) << 16);
    return base | ((uint64_t)(addr >> 4) & 0x3FFF);
}

#define MBARRIER_INIT(addr, cnt) \
    asm volatile("mbarrier.init.shared.b64 [%0], %1;" :: "r"((uint32_t)(addr)), "r"((uint32_t)(cnt)) : "memory")

#define MBARRIER_WAIT_PARITY(addr, parity) do { \
    uint32_t _mbar = (uint32_t)(addr); \
    uint32_t _par = (uint32_t)(parity); \
    uint32_t _done; \
    asm volatile("{\n\t.reg .pred p;\n\t" \
        "mbarrier.try_wait.parity.acquire.cta.shared::cta.b64 p, [%1], %2;\n\t" \
        "selp.b32 %0, 1, 0, p;\n\t}" : "=r"(_done) : "r"(_mbar), "r"(_par) : "memory"); \
    if (!_done) { \
        asm volatile("{\n\t.reg .pred P1;\n\t" \
            "WAIT_LOOP_%=:\n\t" \
            "mbarrier.try_wait.parity.acquire.cta.shared::cta.b64 P1, [%0], %1, 0x989680;\n\t" \
            "@P1 bra.uni WAIT_DONE_%=;\n\t" \
            "bra.uni WAIT_LOOP_%=;\n\t" \
            "WAIT_DONE_%=:\n\t}" :: "r"(_mbar), "r"(_par) : "memory"); \
    } \
} while (0)

#if HAS_TC
#define TCGEN05_ALLOC(smem_addr, nCols) \
    asm volatile("tcgen05.alloc.cta_group::1.sync.aligned.shared::cta.b32 [%0], %1;" \
        :: "r"((uint32_t)(smem_addr)), "r"((uint32_t)(nCols)) : "memory")
#define TCGEN05_DEALLOC(tmem, nCols) \
    asm volatile("tcgen05.dealloc.cta_group::1.sync.aligned.b32 %0, %1;" :: "r"(tmem), "r"((uint32_t)(nCols)))
#define TCGEN05_COMMIT(mbar) \
    asm volatile("tcgen05.commit.cta_group::1.mbarrier::arrive::one.shared::cluster.b64 [%0];" \
        :: "r"((uint32_t)(mbar)) : "memory")
#define TCGEN05_FENCE_AFTER() asm volatile("tcgen05.fence::after_thread_sync;" ::: "memory")
#define TCGEN05_WAIT_LD() asm volatile("tcgen05.wait::ld.sync.aligned;" ::: "memory")

#define TCGEN05_LD_32X32B_X32(r, tmem_addr) \
    asm volatile( \
        "tcgen05.ld.sync.aligned.32x32b.x32.b32 " \
        "{%0, %1, %2, %3, %4, %5, %6, %7, " \
        " %8, %9, %10, %11, %12, %13, %14, %15, " \
        " %16, %17, %18, %19, %20, %21, %22, %23, " \
        " %24, %25, %26, %27, %28, %29, %30, %31}, [%32];" \
        : "=r"((r)[0]),  "=r"((r)[1]),  "=r"((r)[2]),  "=r"((r)[3]), \
          "=r"((r)[4]),  "=r"((r)[5]),  "=r"((r)[6]),  "=r"((r)[7]), \
          "=r"((r)[8]),  "=r"((r)[9]),  "=r"((r)[10]), "=r"((r)[11]), \
          "=r"((r)[12]), "=r"((r)[13]), "=r"((r)[14]), "=r"((r)[15]), \
          "=r"((r)[16]), "=r"((r)[17]), "=r"((r)[18]), "=r"((r)[19]), \
          "=r"((r)[20]), "=r"((r)[21]), "=r"((r)[22]), "=r"((r)[23]), \
          "=r"((r)[24]), "=r"((r)[25]), "=r"((r)[26]), "=r"((r)[27]), \
          "=r"((r)[28]), "=r"((r)[29]), "=r"((r)[30]), "=r"((r)[31]) \
        : "r"(tmem_addr))

__device__ __forceinline__ void mma_bf16_ss(uint32_t d, uint64_t ad, uint64_t bd,
                                            uint32_t idesc, uint32_t en) {
    asm volatile(
        "{\n\t.reg .pred p;\n\tsetp.ne.u32 p, %5, 0;\n\t"
        "tcgen05.mma.cta_group::1.kind::f16 [%0], %1, %2, %3, {%4, %4, %4, %4}, p;\n\t}"
        :: "r"(d), "l"(ad), "l"(bd), "r"(idesc), "r"(0u), "r"(en) : "memory");
}
#endif // HAS_TC

// ---------------- prep kernels ----------------
__global__ void split_kernel(const float* __restrict__ in, bf16* __restrict__ hi,
                             bf16* __restrict__ lo, size_t n) {
    size_t i = (size_t)blockIdx.x * 256 + threadIdx.x;
    if (i < n) {
        float v = in[i];
        bf16 h = __float2bfloat16(v);
        hi[i] = h;
        lo[i] = __float2bfloat16(v - __bfloat162float(h));
    }
}
// out[n*Kw+k] = W[(rowOff+k)*ldW + n]  (transpose + split)
__global__ void tsplit_kernel(const float* __restrict__ W, bf16* __restrict__ hi,
                              bf16* __restrict__ lo, int Kw, int Nw, int rowOff, int ldW) {
    int i = blockIdx.x * 256 + threadIdx.x;
    if (i < Kw * Nw) {
        int n = i / Kw, k = i - n * Kw;
        float v = W[(size_t)(rowOff + k) * ldW + n];
        bf16 h = __float2bfloat16(v);
        hi[i] = h;
        lo[i] = __float2bfloat16(v - __bfloat162float(h));
    }
}

// ---------------- split-bf16 tcgen05 GEMM, BM=128, BN<=256, BK=64 ----------------
#define MMK_STAGES 2
#define STAGE_BYTES 98304        // A hi/lo 32KB + B hi/lo 64KB
#define HDR_BYTES 8192
#define SMEM_TOTAL_MM (HDR_BYTES + MMK_STAGES * STAGE_BYTES)
#define CPITCH 65

template<bool BIAS, bool GELU_, bool WF32, bool WHILO>
__global__ __launch_bounds__(256, 1) void mm_kernel(
    const bf16* __restrict__ Ahi, const bf16* __restrict__ Alo,
    const bf16* __restrict__ Bhi, const bf16* __restrict__ Blo,
    const float* __restrict__ bias,
    float* __restrict__ Cf, bf16* __restrict__ Chi, bf16* __restrict__ Clo,
    int N, int K)
{
#if HAS_TC
    extern __shared__ char dsm[];
    const int tid = threadIdx.x;
    const int wid = tid >> 5;
    const uint32_t sb = smem_u32(dsm);
    const int mBase = blockIdx.y * 128;
    const int nBase = blockIdx.x * 256;
    const int nValid = min(256, N - nBase);

    if (tid == 0) {
        for (int s = 0; s < MMK_STAGES; s++) MBARRIER_INIT(sb + 16 + s * 8, 1);
    }
    if (wid == 0) TCGEN05_ALLOC(sb, 256);
    __syncthreads();
    uint32_t tmem;
    asm volatile("ld.shared.b32 %0, [%1];" : "=r"(tmem) : "r"(sb));

    const uint32_t idesc = (1u << 4) | (1u << 7) | (1u << 10) |
                           ((uint32_t)(nValid >> 3) << 17) | (8u << 24);
    const int NC = (K + 63) >> 6;

    for (int c = 0; c < NC; c++) {
        int s = c & 1;
        if (c >= MMK_STAGES) {
            MBARRIER_WAIT_PARITY(sb + 16 + s * 8, ((c >> 1) - 1) & 1);
        }
        char* stg = dsm + HDR_BYTES + s * STAGE_BYTES;
        int k0 = c << 6;
        // ---- A planes (128 x 64) ----
#pragma unroll
        for (int i = 0; i < 4; i++) {
            int idx = i * 256 + tid;
            int row = idx >> 3, seg = idx & 7;
            int col = k0 + seg * 8;
            if (col < K) {
                size_t off = (size_t)(mBase + row) * K + col;
                uint4 vh = *(const uint4*)(Ahi + off);
                uint4 vl = *(const uint4*)(Alo + off);
                uint32_t sw = SW128(row * 128 + seg * 16);
                *(uint4*)(stg + sw) = vh;
                *(uint4*)(stg + 16384 + sw) = vl;
            }
        }
        // ---- B planes (nValid x 64) ----
#pragma unroll
        for (int i = 0; i < 8; i++) {
            int idx = i * 256 + tid;
            int row = idx >> 3, seg = idx & 7;
            int col = k0 + seg * 8;
            if (row < nValid && col < K) {
                size_t off = (size_t)(nBase + row) * K + col;
                uint4 vh = *(const uint4*)(Bhi + off);
                uint4 vl = *(const uint4*)(Blo + off);
                uint32_t sw = SW128(row * 128 + seg * 16);
                *(uint4*)(stg + 32768 + sw) = vh;
                *(uint4*)(stg + 65536 + sw) = vl;
            }
        }
        asm volatile("fence.proxy.async.shared::cta;" ::: "memory");
        __syncthreads();
        if (wid == 0 && elect1()) {
            uint32_t sg = sb + HDR_BYTES + s * STAGE_BYTES;
            uint64_t dAh = mk_desc(sg);
            uint64_t dAl = mk_desc(sg + 16384);
            uint64_t dBh = mk_desc(sg + 32768);
            uint64_t dBl = mk_desc(sg + 65536);
            int ksteps = min(4, (K - k0 + 15) >> 4);
            for (int ks = 0; ks < ksteps; ks++) {
                uint64_t o = (uint64_t)(ks * 2);
                mma_bf16_ss(tmem, dAh + o, dBh + o, idesc, (c | ks) ? 1u : 0u);
                mma_bf16_ss(tmem, dAh + o, dBl + o, idesc, 1u);
                mma_bf16_ss(tmem, dAl + o, dBh + o, idesc, 1u);
            }
            TCGEN05_COMMIT(sb + 16 + s * 8);
        }
    }
    {
        int lc = NC - 1;
        MBARRIER_WAIT_PARITY(sb + 16 + (lc & 1) * 8, (lc >> 1) & 1);
    }
    TCGEN05_FENCE_AFTER();

    // ---- epilogue ----
    {
        int sub = wid & 3, cg = wid >> 2;
        int lane = tid & 31;
        float* cst = (float*)(dsm + HDR_BYTES);
        for (int cb0 = 0; cb0 < nValid; cb0 += 64) {
            int cb = cb0 + cg * 32;
            if (cb < nValid) {
                uint32_t regs[32];
                TCGEN05_LD_32X32B_X32(regs, tmem + cb);
                TCGEN05_WAIT_LD();
                int r = sub * 32 + lane;
#pragma unroll
                for (int j = 0; j < 32; j++) {
                    int col = cb + j;
                    if (col < nValid) {
                        float v = __uint_as_float(regs[j]);
                        if (BIAS) v += bias[nBase + col];
                        if (GELU_) v = gelu_tanh(v);
                        cst[r * CPITCH + (cg * 32 + j)] = v;
                    }
                }
            }
            __syncthreads();
            int cw = min(64, nValid - cb0);
            for (int i = tid; i < 128 * cw; i += 256) {
                int row = i / cw, col = i - row * cw;
                float v = cst[row * CPITCH + col];
                size_t gr = (size_t)(mBase + row);
                int gc = nBase + cb0 + col;
                if (WF32) Cf[gr * N + gc] = v;
                if (WHILO) {
                    bf16 h = __float2bfloat16(v);
                    Chi[gr * N + gc] = h;
                    Clo[gr * N + gc] = __float2bfloat16(v - __bfloat162float(h));
                }
            }
            __syncthreads();
        }
    }
    __syncthreads();
    if (wid == 0) TCGEN05_DEALLOC(tmem, 256);

#else // !HAS_TC — naive correct fallback (compile-only for non-'a' PTX pass)
    const int tid = threadIdx.x;
    const int mBase = blockIdx.y * 128;
    const int nBase = blockIdx.x * 256;
    const int nValid = min(256, N - nBase);
    if (tid >= 128) return;
    int row = mBase + tid;
    for (int col = 0; col < nValid; col++) {
        int gc = nBase + col;
        float acc = 0.f;
        for (int k = 0; k < K; k++) {
            size_t off = (size_t)row * K + k;
            float a = __bfloat162float(Ahi[off]) + __bfloat162float(Alo[off]);
            size_t bo = (size_t)gc * K + k;
            float bb = __bfloat162float(Bhi[bo]) + __bfloat162float(Blo[bo]);
            acc += a * bb;
        }
        if (BIAS) acc += bias[gc];
        if (GELU_) acc = gelu_tanh(acc);
        if (WF32) Cf[(size_t)row * N + gc] = acc;
        if (WHILO) {
            bf16 h = __float2bfloat16(acc);
            Chi[(size_t)row * N + gc] = h;
            Clo[(size_t)row * N + gc] = __float2bfloat16(acc - __bfloat162float(h));
        }
    }
#endif
}

// ---------------- fused head2: one CTA owns all N=400 columns ----------------
// A row r = gelu(U[sn]+V[dn]+b1), K=800.  Two TMEM accumulators (cols 0-199 /
// 200-399, idesc N=200).  A double-buffered, B single-buffered.  Epilogue:
// gelu(.+b2) dot W3 + b3 -> pred directly.
#define H2_HDR 8192
#define H2_ASTAGE 32768                 // A hi 16KB + lo 16KB
#define H2_BHALF 51200                  // one N-half: hi 25.6KB + lo 25.6KB
#define H2_BBASE (H2_HDR + 2 * H2_ASTAGE)
#define H2_SMEM (H2_BBASE + 2 * H2_BHALF)   // 176128

__global__ __launch_bounds__(256, 1) void head2_kernel(
    const float* __restrict__ U, const float* __restrict__ V,
    const bf16* __restrict__ Bhi, const bf16* __restrict__ Blo,   // h2t [400][800]
    const float* __restrict__ b1, const float* __restrict__ b2,
    const float* __restrict__ w3, const float* __restrict__ b3,
    const int* __restrict__ src0, const int* __restrict__ dst0,
    float* __restrict__ pred)
{
#if HAS_TC
    extern __shared__ char dsm[];
    const int tid = threadIdx.x;
    const int wid = tid >> 5;
    const uint32_t sb = smem_u32(dsm);
    const int mBase = blockIdx.x * 128;
    const int K = PAIRD;                  // 800
    const int NC = 13;
    int* sSrc = (int*)(dsm + 64);
    int* sDst = (int*)(dsm + 576);
    float* sw3 = (float*)(dsm + 1152);    // 1200 floats

    if (tid == 0) { MBARRIER_INIT(sb + 16, 1); MBARRIER_INIT(sb + 24, 1); }
    if (wid == 0) TCGEN05_ALLOC(sb, 512);
    if (tid < 128) {
        int r = mBase + tid;
        int e = r & (EE - 1), b = r >> 14;
        sSrc[tid] = (b << 10) + src0[e];
        sDst[tid] = (b << 10) + dst0[e];
    }
    for (int i = tid; i < 1200; i += 256) sw3[i] = w3[i];
    __syncthreads();
    uint32_t tmem;
    asm volatile("ld.shared.b32 %0, [%1];" : "=r"(tmem) : "r"(sb));

    const uint32_t idesc = (1u << 4) | (1u << 7) | (1u << 10) | (25u << 17) | (8u << 24); // N=200

    for (int c = 0; c < NC; c++) {
        int k0 = c << 6;
        char* astg = dsm + H2_HDR + (c & 1) * H2_ASTAGE;
        // A buffer (c&1) free when MMA(c-2) done
        if (c >= 2) MBARRIER_WAIT_PARITY(sb + 16 + (c & 1) * 8, ((c >> 1) - 1) & 1);
        // ---- A-gen: gelu(U[sn]+V[dn]+b1), hi/lo split, ONCE per chunk ----
#pragma unroll
        for (int i = 0; i < 4; i++) {
            int idx = i * 256 + tid;
            int row = idx >> 3, seg = idx & 7;
            int col = k0 + seg * 8;
            if (col < K) {
                int sn = sSrc[row], dn = sDst[row];
                const float* up = U + (size_t)sn * PAIRD + col;
                const float* vp = V + (size_t)dn * PAIRD + col;
                float4 u0 = *(const float4*)up, u1 = *(const float4*)(up + 4);
                float4 v0 = *(const float4*)vp, v1 = *(const float4*)(vp + 4);
                float4 b0 = *(const float4*)(b1 + col);
                float4 b1v = *(const float4*)(b1 + col + 4);
                float r8[8];
                r8[0] = gelu_tanh(u0.x + v0.x + b0.x);
                r8[1] = gelu_tanh(u0.y + v0.y + b0.y);
                r8[2] = gelu_tanh(u0.z + v0.z + b0.z);
                r8[3] = gelu_tanh(u0.w + v0.w + b0.w);
                r8[4] = gelu_tanh(u1.x + v1.x + b1v.x);
                r8[5] = gelu_tanh(u1.y + v1.y + b1v.y);
                r8[6] = gelu_tanh(u1.z + v1.z + b1v.z);
                r8[7] = gelu_tanh(u1.w + v1.w + b1v.w);
                uint32_t hw[4], lw[4];
#pragma unroll
                for (int q = 0; q < 4; q++) {
                    bf16 h0 = __float2bfloat16(r8[q*2+0]);
                    bf16 h1 = __float2bfloat16(r8[q*2+1]);
                    bf16 l0 = __float2bfloat16(r8[q*2+0] - __bfloat162float(h0));
                    bf16 l1 = __float2bfloat16(r8[q*2+1] - __bfloat162float(h1));
                    hw[q] = ((uint32_t)__bfloat16_as_ushort(h1) << 16) | __bfloat16_as_ushort(h0);
                    lw[q] = ((uint32_t)__bfloat16_as_ushort(l1) << 16) | __bfloat16_as_ushort(l0);
                }
                uint32_t sw = SW128(row * 128 + seg * 16);
                *(uint4*)(astg + sw) = make_uint4(hw[0], hw[1], hw[2], hw[3]);
                *(uint4*)(astg + 16384 + sw) = make_uint4(lw[0], lw[1], lw[2], lw[3]);
            }
        }
        // B buffer free when MMA(c-1) done
        if (c >= 1) MBARRIER_WAIT_PARITY(sb + 16 + ((c - 1) & 1) * 8, ((c - 1) >> 1) & 1);
        // ---- B-load: 400 rows x 64 cols, split by N-half ----
#pragma unroll 1
        for (int i = 0; i < 13; i++) {
            int idx = i * 256 + tid;
            if (idx < 3200) {
                int row = idx >> 3, seg = idx & 7;
                int col = k0 + seg * 8;
                if (col < K) {
                    size_t off = (size_t)row * K + col;
                    uint4 vh = *(const uint4*)(Bhi + off);
                    uint4 vl = *(const uint4*)(Blo + off);
                    int half = (row >= 200);
                    int lrow = row - half * 200;
                    char* bstg = dsm + H2_BBASE + half * H2_BHALF;
                    uint32_t sw = SW128(lrow * 128 + seg * 16);
                    *(uint4*)(bstg + sw) = vh;
                    *(uint4*)(bstg + 25600 + sw) = vl;
                }
            }
        }
        asm volatile("fence.proxy.async.shared::cta;" ::: "memory");
        __syncthreads();
        if (wid == 0 && elect1()) {
            uint32_t ag = sb + H2_HDR + (c & 1) * H2_ASTAGE;
            uint64_t dAh = mk_desc(ag);
            uint64_t dAl = mk_desc(ag + 16384);
            int ksteps = min(4, (K - k0) >> 4);
            for (int half = 0; half < 2; half++) {
                uint32_t bg = sb + H2_BBASE + half * H2_BHALF;
                uint64_t dBh = mk_desc(bg);
                uint64_t dBl = mk_desc(bg + 25600);
                uint32_t d = tmem + half * 200;
                for (int ks = 0; ks < ksteps; ks++) {
                    uint64_t o = (uint64_t)(ks * 2);
                    mma_bf16_ss(d, dAh + o, dBh + o, idesc, (c | ks) ? 1u : 0u);
                    mma_bf16_ss(d, dAh + o, dBl + o, idesc, 1u);
                    mma_bf16_ss(d, dAl + o, dBh + o, idesc, 1u);
                }
            }
            TCGEN05_COMMIT(sb + 16 + (c & 1) * 8);
        }
    }
    // final MMA (c=12): mbar[0], completion index 6 -> parity 0
    MBARRIER_WAIT_PARITY(sb + 16 + ((NC - 1) & 1) * 8, ((NC - 1) >> 1) & 1);
    TCGEN05_FENCE_AFTER();

    // ---- epilogue: gelu(.+b2) dot W3 -> pred ----
    {
        int sub = wid & 3, cg = wid >> 2;
        int lane = tid & 31;
        float* cst = (float*)(dsm + H2_HDR);
        float d0 = 0.f, d1 = 0.f, d2 = 0.f;
        for (int cb0 = 0; cb0 < 400; cb0 += 64) {
            int cb = cb0 + cg * 32;
            if (cb < 400) {
                uint32_t regs[32];
                TCGEN05_LD_32X32B_X32(regs, tmem + cb);
                TCGEN05_WAIT_LD();
                int r = sub * 32 + lane;
#pragma unroll
                for (int j = 0; j < 32; j++) {
                    int col = cb + j;
                    if (col < 400) {
                        float v = __uint_as_float(regs[j]) + b2[col];
                        v = gelu_tanh(v);
                        cst[r * CPITCH + (cg * 32 + j)] = v;
                    }
                }
            }
            __syncthreads();
            int cw = min(64, 400 - cb0);
            if (tid < 128) {
                for (int col = 0; col < cw; col++) {
                    float v = cst[tid * CPITCH + col];
                    int wc = (cb0 + col) * 3;
                    d0 += v * sw3[wc + 0];
                    d1 += v * sw3[wc + 1];
                    d2 += v * sw3[wc + 2];
                }
            }
            __syncthreads();
        }
        if (tid < 128) {
            size_t r = (size_t)(mBase + tid);
            pred[r * 3 + 0] = d0 + b3[0];
            pred[r * 3 + 1] = d1 + b3[1];
            pred[r * 3 + 2] = d2 + b3[2];
        }
    }
    __syncthreads();
    if (wid == 0) TCGEN05_DEALLOC(tmem, 512);

#else // !HAS_TC — naive correct fallback (compile-only)
    const int tid = threadIdx.x;
    const int mBase = blockIdx.x * 128;
    if (tid >= 128) return;
    int row = mBase + tid;
    int e = row & (EE - 1), b = row >> 14;
    int sn = (b << 10) + src0[e];
    int dn = (b << 10) + dst0[e];
    float d0 = 0.f, d1 = 0.f, d2 = 0.f;
    for (int col = 0; col < 400; col++) {
        float acc = 0.f;
        for (int k = 0; k < PAIRD; k++) {
            float a = gelu_tanh(U[(size_t)sn * PAIRD + k] + V[(size_t)dn * PAIRD + k] + b1[k]);
            size_t bo = (size_t)col * PAIRD + k;
            float bb = __bfloat162float(Bhi[bo]) + __bfloat162float(Blo[bo]);
            acc += a * bb;
        }
        acc = gelu_tanh(acc + b2[col]);
        d0 += acc * w3[col * 3 + 0];
        d1 += acc * w3[col * 3 + 1];
        d2 += acc * w3[col * 3 + 2];
    }
    pred[(size_t)row * 3 + 0] = d0 + b3[0];
    pred[(size_t)row * 3 + 1] = d1 + b3[1];
    pred[(size_t)row * 3 + 2] = d2 + b3[2];
#endif
}

// ---------------- attention scores ----------------
__global__ void attn_score_kernel(const float* __restrict__ wh,
                                  const float* __restrict__ att_src,
                                  const float* __restrict__ att_dst,
                                  float* __restrict__ as_, float* __restrict__ ad_)
{
    int bn = blockIdx.x;
    int h = threadIdx.x >> 5, lane = threadIdx.x & 31;
    const float* w = wh + (size_t)bn * OUTD + h * 200;
    float s = 0.f, d = 0.f;
    for (int f = lane; f < 200; f += 32) {
        float v = w[f];
        s += v * att_src[h * 200 + f];
        d += v * att_dst[h * 200 + f];
    }
#pragma unroll
    for (int o = 16; o; o >>= 1) {
        s += __shfl_down_sync(0xffffffffu, s, o);
        d += __shfl_down_sync(0xffffffffu, d, o);
    }
    if (lane == 0) { as_[bn * 2 + h] = s; ad_[bn * 2 + h] = d; }
}

// ---------------- CSR build ----------------
__global__ void zero_counts_kernel(int* counts) { counts[threadIdx.x] = 0; }

__global__ void count_kernel(const int* __restrict__ edges, int* __restrict__ counts) {
    int et = blockIdx.x * 256 + threadIdx.x;
    if (et >= ETOT) return;
    int dst = (et < EE) ? edges[EE + et] : (et - EE);
    atomicAdd(&counts[dst], 1);
}

__global__ void scan_kernel(const int* __restrict__ counts, int* __restrict__ rowstart,
                            int* __restrict__ fill) {
    __shared__ int s[NN];
    int t = threadIdx.x;
    int c = counts[t];
    s[t] = c;
    __syncthreads();
    for (int o = 1; o < NN; o <<= 1) {
        int v = (t >= o) ? s[t - o] : 0;
        __syncthreads();
        s[t] += v;
        __syncthreads();
    }
    rowstart[t + 1] = s[t];
    if (t == 0) rowstart[0] = 0;
    fill[t] = s[t] - c;
}

__global__ void scatter_kernel(const int* __restrict__ edges, int* __restrict__ fill,
                               int* __restrict__ csrsrc) {
    int et = blockIdx.x * 256 + threadIdx.x;
    if (et >= ETOT) return;
    int src = (et < EE) ? edges[et] : (et - EE);
    int dst = (et < EE) ? edges[EE + et] : (et - EE);
    int pos = atomicAdd(&fill[dst], 1);
    csrsrc[pos] = src;
}

// ---------------- GAT softmax + aggregation + residual ----------------
#define CHUNK 256
__global__ void gat_kernel(const float* __restrict__ wh, const float* __restrict__ as_,
                           const float* __restrict__ ad_, const float* __restrict__ enc,
                           const float* __restrict__ gat_b,
                           const int* __restrict__ rowstart, const int* __restrict__ csrsrc,
                           float* __restrict__ feat, bf16* __restrict__ feat_hi,
                           bf16* __restrict__ feat_lo)
{
    __shared__ float red0[256], red1[256];
    __shared__ int   s_src[CHUNK];
    __shared__ float s_c0[CHUNK], s_c1[CHUNK];
    __shared__ float sh_m0, sh_m1, sh_z0, sh_z1;

    int bn = blockIdx.x;
    int b = bn >> 10, n = bn & 1023;
    int tid = threadIdx.x;
    int start = rowstart[n];
    int deg = rowstart[n + 1] - start;

    float ad0 = ad_[bn * 2 + 0], ad1 = ad_[bn * 2 + 1];

    float m0 = -1e30f, m1 = -1e30f;
    for (int i = tid; i < deg; i += 256) {
        int s = csrsrc[start + i];
        int sb2 = (b << 10) + s;
        float e0 = as_[sb2 * 2 + 0] + ad0; e0 = (e0 > 0.f) ? e0 : 0.2f * e0;
        float e1 = as_[sb2 * 2 + 1] + ad1; e1 = (e1 > 0.f) ? e1 : 0.2f * e1;
        m0 = fmaxf(m0, e0); m1 = fmaxf(m1, e1);
    }
    red0[tid] = m0; red1[tid] = m1;
    __syncthreads();
    for (int o = 128; o; o >>= 1) {
        if (tid < o) {
            red0[tid] = fmaxf(red0[tid], red0[tid + o]);
            red1[tid] = fmaxf(red1[tid], red1[tid + o]);
        }
        __syncthreads();
    }
    if (tid == 0) { sh_m0 = red0[0]; sh_m1 = red1[0]; }
    __syncthreads();
    m0 = sh_m0; m1 = sh_m1;
    __syncthreads();

    float z0 = 0.f, z1 = 0.f;
    for (int i = tid; i < deg; i += 256) {
        int s = csrsrc[start + i];
        int sb2 = (b << 10) + s;
        float e0 = as_[sb2 * 2 + 0] + ad0; e0 = (e0 > 0.f) ? e0 : 0.2f * e0;
        float e1 = as_[sb2 * 2 + 1] + ad1; e1 = (e1 > 0.f) ? e1 : 0.2f * e1;
        z0 += expf(e0 - m0);
        z1 += expf(e1 - m1);
    }
    red0[tid] = z0; red1[tid] = z1;
    __syncthreads();
    for (int o = 128; o; o >>= 1) {
        if (tid < o) { red0[tid] += red0[tid + o]; red1[tid] += red1[tid + o]; }
        __syncthreads();
    }
    if (tid == 0) { sh_z0 = red0[0]; sh_z1 = red1[0]; }
    __syncthreads();
    z0 = sh_z0; z1 = sh_z1;
    float inv0 = 1.f / z0, inv1 = 1.f / z1;

    float acc0 = 0.f, acc1 = 0.f;
    for (int c0 = 0; c0 < deg; c0 += CHUNK) {
        int cn = min(CHUNK, deg - c0);
        __syncthreads();
        if (tid < cn) {
            int s = csrsrc[start + c0 + tid];
            int sb2 = (b << 10) + s;
            float e0 = as_[sb2 * 2 + 0] + ad0; e0 = (e0 > 0.f) ? e0 : 0.2f * e0;
            float e1 = as_[sb2 * 2 + 1] + ad1; e1 = (e1 > 0.f) ? e1 : 0.2f * e1;
            s_src[tid] = sb2;
            s_c0[tid] = expf(e0 - m0) * inv0;
            s_c1[tid] = expf(e1 - m1) * inv1;
        }
        __syncthreads();
        for (int i = 0; i < cn; i++) {
            const float* whrow = wh + (size_t)s_src[i] * OUTD;
            float coef = (tid < 200) ? s_c0[i] : s_c1[i];
            acc0 += coef * whrow[tid];
            if (tid < OUTD - 256) acc1 += s_c1[i] * whrow[tid + 256];
        }
    }

    size_t base = (size_t)bn * OUTD;
    {
        float v = enc[base + tid] + acc0 + gat_b[tid];
        feat[base + tid] = v;
        bf16 h = __float2bfloat16(v);
        feat_hi[base + tid] = h;
        feat_lo[base + tid] = __float2bfloat16(v - __bfloat162float(h));
    }
    if (tid < OUTD - 256) {
        float v = enc[base + tid + 256] + acc1 + gat_b[tid + 256];
        feat[base + tid + 256] = v;
        bf16 h = __float2bfloat16(v);
        feat_hi[base + tid + 256] = h;
        feat_lo[base + tid + 256] = __float2bfloat16(v - __bfloat162float(h));
    }
}

// ---------------- launch ----------------
extern "C" void kernel_launch(void* const* d_in, const int* in_sizes, int n_in,
                              void* d_out, int out_size)
{
    const float* X       = (const float*)d_in[0];
    const int*   edges   = (const int*)  d_in[1];
    const float* enc_w1  = (const float*)d_in[2];
    const float* enc_b1  = (const float*)d_in[3];
    const float* enc_w2  = (const float*)d_in[4];
    const float* enc_b2  = (const float*)d_in[5];
    const float* gat_w   = (const float*)d_in[6];
    const float* att_src = (const float*)d_in[7];
    const float* att_dst = (const float*)d_in[8];
    const float* gat_b   = (const float*)d_in[9];
    const float* h_w1    = (const float*)d_in[10];
    const float* h_b1    = (const float*)d_in[11];
    const float* h_w2    = (const float*)d_in[12];
    const float* h_b2    = (const float*)d_in[13];
    const float* h_w3    = (const float*)d_in[14];
    const float* h_b3    = (const float*)d_in[15];

    float* out  = (float*)d_out;
    float* feat = out;
    float* pred = out + FEAT_ELEMS;

    bf16 *Xhi, *Xlo, *hid_hi, *hid_lo, *enc_hi, *enc_lo, *feat_hi, *feat_lo;
    bf16 *w1t_hi, *w1t_lo, *w2t_hi, *w2t_lo, *wgt_hi, *wgt_lo;
    bf16 *w1a_hi, *w1a_lo, *w1b_hi, *w1b_lo, *h2t_hi, *h2t_lo;
    float *enc, *wh, *as_, *ad_, *U, *V;
    int *counts, *rowstart, *fill, *csrsrc;
    cudaGetSymbolAddress((void**)&Xhi, g_Xhi);       cudaGetSymbolAddress((void**)&Xlo, g_Xlo);
    cudaGetSymbolAddress((void**)&hid_hi, g_hid_hi); cudaGetSymbolAddress((void**)&hid_lo, g_hid_lo);
    cudaGetSymbolAddress((void**)&enc, g_enc);
    cudaGetSymbolAddress((void**)&enc_hi, g_enc_hi); cudaGetSymbolAddress((void**)&enc_lo, g_enc_lo);
    cudaGetSymbolAddress((void**)&wh, g_wh);
    cudaGetSymbolAddress((void**)&feat_hi, g_feat_hi); cudaGetSymbolAddress((void**)&feat_lo, g_feat_lo);
    cudaGetSymbolAddress((void**)&U, g_U);           cudaGetSymbolAddress((void**)&V, g_V);
    cudaGetSymbolAddress((void**)&w1t_hi, g_w1t_hi); cudaGetSymbolAddress((void**)&w1t_lo, g_w1t_lo);
    cudaGetSymbolAddress((void**)&w2t_hi, g_w2t_hi); cudaGetSymbolAddress((void**)&w2t_lo, g_w2t_lo);
    cudaGetSymbolAddress((void**)&wgt_hi, g_wgt_hi); cudaGetSymbolAddress((void**)&wgt_lo, g_wgt_lo);
    cudaGetSymbolAddress((void**)&w1a_hi, g_w1a_hi); cudaGetSymbolAddress((void**)&w1a_lo, g_w1a_lo);
    cudaGetSymbolAddress((void**)&w1b_hi, g_w1b_hi); cudaGetSymbolAddress((void**)&w1b_lo, g_w1b_lo);
    cudaGetSymbolAddress((void**)&h2t_hi, g_h2t_hi); cudaGetSymbolAddress((void**)&h2t_lo, g_h2t_lo);
    cudaGetSymbolAddress((void**)&as_, g_as);        cudaGetSymbolAddress((void**)&ad_, g_ad);
    cudaGetSymbolAddress((void**)&counts, g_counts); cudaGetSymbolAddress((void**)&rowstart, g_rowstart);
    cudaGetSymbolAddress((void**)&fill, g_fill);     cudaGetSymbolAddress((void**)&csrsrc, g_csrsrc);

    const int* src0 = edges;
    const int* dst0 = edges + EE;

    cudaFuncSetAttribute(mm_kernel<true ,true ,false,true >, cudaFuncAttributeMaxDynamicSharedMemorySize, SMEM_TOTAL_MM);
    cudaFuncSetAttribute(mm_kernel<true ,false,true ,true >, cudaFuncAttributeMaxDynamicSharedMemorySize, SMEM_TOTAL_MM);
    cudaFuncSetAttribute(mm_kernel<false,false,true ,false>, cudaFuncAttributeMaxDynamicSharedMemorySize, SMEM_TOTAL_MM);
    cudaFuncSetAttribute(head2_kernel, cudaFuncAttributeMaxDynamicSharedMemorySize, H2_SMEM);

    // ---- prep: split X, transpose+split weights ----
    {
        size_t nX = (size_t)BNR * IND;
        split_kernel<<<(unsigned)((nX + 255) / 256), 256>>>(X, Xhi, Xlo, nX);
        tsplit_kernel<<<(IND * HIDD + 255) / 256, 256>>>(enc_w1, w1t_hi, w1t_lo, IND, HIDD, 0, HIDD);
        tsplit_kernel<<<(HIDD * OUTD + 255) / 256, 256>>>(enc_w2, w2t_hi, w2t_lo, HIDD, OUTD, 0, OUTD);
        tsplit_kernel<<<(OUTD * OUTD + 255) / 256, 256>>>(gat_w, wgt_hi, wgt_lo, OUTD, OUTD, 0, OUTD);
        tsplit_kernel<<<(OUTD * PAIRD + 255) / 256, 256>>>(h_w1, w1a_hi, w1a_lo, OUTD, PAIRD, 0, PAIRD);
        tsplit_kernel<<<(OUTD * PAIRD + 255) / 256, 256>>>(h_w1, w1b_hi, w1b_lo, OUTD, PAIRD, OUTD, PAIRD);
        tsplit_kernel<<<(PAIRD * (PAIRD/2) + 255) / 256, 256>>>(h_w2, h2t_hi, h2t_lo, PAIRD, PAIRD/2, 0, PAIRD/2);
    }

    // 1) enc1: [32768,768] -> [32768,512], GELU, write hid hi/lo
    mm_kernel<true,true,false,true><<<dim3(2, BNR/128), 256, SMEM_TOTAL_MM>>>(
        Xhi, Xlo, w1t_hi, w1t_lo, enc_b1, nullptr, hid_hi, hid_lo, HIDD, IND);
    // 2) enc2: [32768,512] -> [32768,400], write enc f32 + hi/lo
    mm_kernel<true,false,true,true><<<dim3(2, BNR/128), 256, SMEM_TOTAL_MM>>>(
        hid_hi, hid_lo, w2t_hi, w2t_lo, enc_b2, enc, enc_hi, enc_lo, OUTD, HIDD);
    // 3) wh = enc @ gat_w
    mm_kernel<false,false,true,false><<<dim3(2, BNR/128), 256, SMEM_TOTAL_MM>>>(
        enc_hi, enc_lo, wgt_hi, wgt_lo, nullptr, wh, nullptr, nullptr, OUTD, OUTD);
    // 4) attention scores
    attn_score_kernel<<<BNR, 64>>>(wh, att_src, att_dst, as_, ad_);
    // 5) CSR build
    zero_counts_kernel<<<1, NN>>>(counts);
    count_kernel<<<(ETOT + 255) / 256, 256>>>(edges, counts);
    scan_kernel<<<1, NN>>>(counts, rowstart, fill);
    scatter_kernel<<<(ETOT + 255) / 256, 256>>>(edges, fill, csrsrc);
    // 6) GAT aggregate + residual -> feat (output) + feat hi/lo
    gat_kernel<<<BNR, 256>>>(wh, as_, ad_, enc, gat_b, rowstart, csrsrc, feat, feat_hi, feat_lo);
    // 7a) U = feat @ W1top: [32768,400] x [400,800]
    mm_kernel<false,false,true,false><<<dim3(4, BNR/128), 256, SMEM_TOTAL_MM>>>(
        feat_hi, feat_lo, w1a_hi, w1a_lo, nullptr, U, nullptr, nullptr, PAIRD, OUTD);
    // 7b) V = feat @ W1bot
    mm_kernel<false,false,true,false><<<dim3(4, BNR/128), 256, SMEM_TOTAL_MM>>>(
        feat_hi, feat_lo, w1b_hi, w1b_lo, nullptr, V, nullptr, nullptr, PAIRD, OUTD);
    // 8) head2 fused single-pass: A-gen once, both N-halves, pred written directly
    head2_kernel<<<BER / 128, 256, H2_SMEM>>>(
        U, V, h2t_hi, h2t_lo, h_b1, h_b2, h_w3, h_b3, src0, dst0, pred);
}